// round 16
// baseline (speedup 1.0000x reference)
#include <cuda_runtime.h>
#include <cuda_fp16.h>
#include <math.h>
#include <stdint.h>

#define Hc  256
#define Wc  256
#define CINc 128
#define HWC (Hc * Wc)

// ---------------- scratch (static device globals; no runtime allocation) ----
__device__ __align__(256) __half g_fh[(size_t)4 * 128 * HWC];  // post-BN features NCHW fp16
__device__ float g_att[(size_t)4 * 2 * HWC];                   // attention logits
__device__ __align__(256) __half g_xh[(size_t)4 * HWC * 128];  // x fp16, NHWC
__device__ __align__(256) __half g_wh[18 * 128 * 64];          // W fp16 [chunk][oc][k]

// ---------------- helpers ----------------------------------------------------
__device__ __forceinline__ uint32_t smem_u32(const void* p) {
    uint32_t a;
    asm("{ .reg .u64 t; cvta.to.shared.u64 t, %1; cvt.u32.u64 %0, t; }" : "=r"(a) : "l"(p));
    return a;
}
__device__ __forceinline__ void cp16(uint32_t dst, const void* src, uint32_t sz) {
    asm volatile("cp.async.cg.shared.global [%0], [%1], 16, %2;"
                 :: "r"(dst), "l"(src), "r"(sz));
}
#define CP_COMMIT() asm volatile("cp.async.commit_group;" ::: "memory")
#define CP_WAIT2()  asm volatile("cp.async.wait_group 2;" ::: "memory")

__device__ __forceinline__ void ldsm_x4(uint32_t* r, uint32_t a) {
    asm volatile("ldmatrix.sync.aligned.m8n8.x4.shared.b16 {%0,%1,%2,%3}, [%4];"
                 : "=r"(r[0]), "=r"(r[1]), "=r"(r[2]), "=r"(r[3]) : "r"(a));
}
__device__ __forceinline__ void mma16816(float* d, const uint32_t* a, const uint32_t* b) {
    asm volatile("mma.sync.aligned.m16n8k16.row.col.f32.f16.f16.f32 "
                 "{%0,%1,%2,%3},{%4,%5,%6,%7},{%8,%9},{%0,%1,%2,%3};"
                 : "+f"(d[0]), "+f"(d[1]), "+f"(d[2]), "+f"(d[3])
                 : "r"(a[0]), "r"(a[1]), "r"(a[2]), "r"(a[3]), "r"(b[0]), "r"(b[1]));
}

// position helper (matches reference)
__device__ __forceinline__ float axis_g(int i, int n) {
    float off = ((n & 1) == 0) ? 0.5f : 0.0f;
    return fabsf((float)i - (float)(n / 2) + off) / (float)(n / 2);
}

// ============================================================================
// prep_x: NCHW fp32 -> NHWC fp16 (smem transpose, coalesced both sides)
//   x read is zero-reuse -> __ldcs; loads batched for MLP
// ============================================================================
__global__ __launch_bounds__(256)
void prep_x_kernel(const float* __restrict__ x)
{
    __shared__ __half s_h[64 * 136];
    int blk = blockIdx.x;
    int bb  = blk >> 10;
    int px0 = (blk & 1023) * 64;
    int tid = threadIdx.x;
    int p = tid & 63, cq = tid >> 6;

    const float* xb = x + (size_t)bb * CINc * HWC + px0 + p;
    float v[32];
    #pragma unroll
    for (int i = 0; i < 32; i++)
        v[i] = __ldcs(xb + (size_t)(i * 4 + cq) * HWC);
    #pragma unroll
    for (int i = 0; i < 32; i++)
        s_h[p * 136 + i * 4 + cq] = __float2half(v[i]);
    __syncthreads();
    for (int i = tid; i < 64 * 16; i += 256) {
        int p2 = i >> 4, j = i & 15;
        uint4 w = *(const uint4*)&s_h[p2 * 136 + j * 8];
        size_t e = ((size_t)bb * HWC + px0 + p2) * 128 + j * 8;
        *(uint4*)(g_xh + e) = w;
    }
}

// ============================================================================
// prep_w: fp32 weights -> fp16, [chunk18][128oc][64k]
// ============================================================================
__global__ void prep_w_kernel(const float* __restrict__ wa, const float* __restrict__ wb)
{
    int idx = blockIdx.x * 256 + threadIdx.x;
    if (idx >= 18 * 128 * 64) return;
    int k  = idx & 63;
    int oc = (idx >> 6) & 127;
    int c  = idx >> 13;
    int t  = c >> 1, hf = c & 1;
    int cin = hf * 64 + k;
    float w = (oc < 64) ? wa[((size_t)oc * CINc + cin) * 9 + t]
                        : wb[((size_t)(oc - 64) * CINc + cin) * 9 + t];
    g_wh[idx] = __float2half(w);
}

// ============================================================================
// conv_mma: implicit GEMM via mma.sync fp16 (single term, fp32 accum)
//   CTA: 128 oc x 128 px; 8 warps (4 m-groups x 2 n-groups), warp tile 32x64
//   2 CTAs/SM (96 KB smem, <=128 regs)
//   K: 18 chunks of 64 (tap x cin-half); cp.async 3-stage pipeline
//   Epilogue: BN fold -> g_fh (fp16), fused 1x1 attention conv -> g_att
// ============================================================================
#define A_W  0
#define B_X  16384
#define STAGE 32768
#define SMEM_TOT (3 * STAGE)

// swizzled 16B offset inside a [row][64k] fp16 tile (row stride 128B)
__device__ __forceinline__ uint32_t swz(int row, int j16) {
    return (uint32_t)(row * 128 + ((j16 ^ (row & 7)) << 4));
}

__global__ __launch_bounds__(256, 2)
void conv_mma_kernel(const float* __restrict__ ba,  const float* __restrict__ bbv,
                     const float* __restrict__ gA,  const float* __restrict__ beA,
                     const float* __restrict__ mA,  const float* __restrict__ vA,
                     const float* __restrict__ gB,  const float* __restrict__ beB,
                     const float* __restrict__ mB,  const float* __restrict__ vB,
                     const float* __restrict__ aw,  const float* __restrict__ abv,
                     const float* __restrict__ bw,  const float* __restrict__ bb2,
                     const float* __restrict__ gA1, const float* __restrict__ beA1,
                     const float* __restrict__ mA1, const float* __restrict__ vA1,
                     const float* __restrict__ gB1, const float* __restrict__ beB1,
                     const float* __restrict__ mB1, const float* __restrict__ vB1)
{
    extern __shared__ char smem[];
    const uint32_t sb = smem_u32(smem);
    const int tid  = threadIdx.x;
    const int wid  = tid >> 5, lane = tid & 31;
    const int bb   = blockIdx.x >> 9;
    const int y    = (blockIdx.x >> 1) & 255;
    const int pxh  = blockIdx.x & 1;          // which 128-px half of the row
    const int m0   = (wid >> 1) * 32;         // warp oc base (4 m-groups)
    const int n0   = (wid & 1) * 64;          // warp px base (2 n-groups)

    float C[2][8][4];
    #pragma unroll
    for (int mt = 0; mt < 2; mt++)
        #pragma unroll
        for (int nt = 0; nt < 8; nt++)
            #pragma unroll
            for (int q = 0; q < 4; q++) C[mt][nt][q] = 0.f;

    // ---- chunk loader: cp.async into stage (c % 3), one commit ----
    auto load_chunk = [&](int c) {
        uint32_t stg = sb + (uint32_t)(c % 3) * STAGE;
        int t  = c >> 1, hf = c & 1;
        int yy = y + t / 3 - 1;
        int dx = t % 3 - 1;
        bool vy = (yy >= 0) && (yy < Hc);
        size_t arow = (size_t)c * 8192;                       // A chunk base (elems)
        size_t brow = ((size_t)(bb * Hc + yy) * Wc) * 128;    // B row base (elems)
        #pragma unroll
        for (int i = 0; i < 4; i++) {                         // A: 128 oc rows
            int idx = tid + i * 256;
            int row = idx >> 3, j = idx & 7;
            cp16(stg + A_W + swz(row, j), g_wh + arow + idx * 8, 16);
        }
        #pragma unroll
        for (int i = 0; i < 4; i++) {                         // B: 128 px rows
            int idx = tid + i * 256;
            int row = idx >> 3, j = idx & 7;
            int xx = pxh * 128 + row + dx;
            bool ok = vy && (xx >= 0) && (xx < Wc);
            size_t e = ok ? (brow + (size_t)xx * 128 + hf * 64 + j * 8) : 0;
            cp16(stg + B_X + swz(row, j), g_xh + e, ok ? 16u : 0u);
        }
        CP_COMMIT();
    };

    // prologue: prefetch chunks 0..2
    load_chunk(0);
    load_chunk(1);
    load_chunk(2);

    for (int c = 0; c < 18; c++) {
        CP_WAIT2();
        __syncthreads();
        const uint32_t stg = sb + (uint32_t)(c % 3) * STAGE;

        #pragma unroll
        for (int kg = 0; kg < 4; kg++) {
            uint32_t ah[2][4];
            #pragma unroll
            for (int mt = 0; mt < 2; mt++) {
                int row = m0 + mt * 16 + (lane & 15);
                int kc  = kg * 2 + (lane >> 4);
                ldsm_x4(ah[mt], stg + A_W + swz(row, kc));
            }
            #pragma unroll
            for (int nq = 0; nq < 4; nq++) {
                uint32_t bx[4];
                int row = n0 + nq * 16 + (lane & 7) + ((lane >> 4) << 3);
                int kc  = kg * 2 + ((lane >> 3) & 1);
                ldsm_x4(bx, stg + B_X + swz(row, kc));
                #pragma unroll
                for (int mt = 0; mt < 2; mt++)
                    #pragma unroll
                    for (int h = 0; h < 2; h++)
                        mma16816(C[mt][nq * 2 + h], ah[mt], &bx[h * 2]);
            }
        }
        __syncthreads();
        if (c + 3 < 18) load_chunk(c + 3);
        else            CP_COMMIT();
    }

    // ---- epilogue: BN fold -> g_fh (fp16), fused 1x1 att conv -> g_att ------
    float* s_p = (float*)smem;               // [4 m-groups][128 px] partials
    const int mg = wid >> 1;                 // m-group: 0,1 = branch a; 2,3 = b

    float scq4[2][2], sh4[2][2], wv4[2][2];
    __half* frow[2][2];
    #pragma unroll
    for (int mt = 0; mt < 2; mt++)
        #pragma unroll
        for (int hr = 0; hr < 2; hr++) {
            int oc = m0 + mt * 16 + (lane >> 2) + hr * 8;
            float sc, sh;
            if (oc < 64) {
                sc = gA[oc] * rsqrtf(vA[oc] + 1e-3f);
                sh = beA[oc] - mA[oc] * sc + ba[oc] * sc;
                wv4[mt][hr] = __ldg(aw + oc);
            } else {
                int o = oc - 64;
                sc = gB[o] * rsqrtf(vB[o] + 1e-3f);
                sh = beB[o] - mB[o] * sc + bbv[o] * sc;
                wv4[mt][hr] = __ldg(bw + o);
            }
            scq4[mt][hr] = sc;
            sh4[mt][hr]  = sh;
            frow[mt][hr] = g_fh + (((size_t)bb * 128 + oc) * Hc + y) * Wc + pxh * 128;
        }

    #pragma unroll
    for (int nt = 0; nt < 8; nt++) {
        int col = n0 + nt * 8 + 2 * (lane & 3);
        float v0 = 0.f, v1 = 0.f;
        #pragma unroll
        for (int mt = 0; mt < 2; mt++)
            #pragma unroll
            for (int hr = 0; hr < 2; hr++) {
                float f0 = C[mt][nt][hr * 2 + 0] * scq4[mt][hr] + sh4[mt][hr];
                float f1 = C[mt][nt][hr * 2 + 1] * scq4[mt][hr] + sh4[mt][hr];
                *(__half2*)(frow[mt][hr] + col) = __floats2half2_rn(f0, f1);
                v0 += wv4[mt][hr] * f0;
                v1 += wv4[mt][hr] * f1;
            }
        // reduce across the 8 row-lanes (same lane&3)
        #pragma unroll
        for (int d = 16; d >= 4; d >>= 1) {
            v0 += __shfl_down_sync(0xffffffffu, v0, d);
            v1 += __shfl_down_sync(0xffffffffu, v1, d);
        }
        if ((lane >> 2) == 0) {
            s_p[mg * 128 + col]     = v0;
            s_p[mg * 128 + col + 1] = v1;
        }
    }
    __syncthreads();

    // finalize attention logits: +gh/gw terms +bias, BN, store (256 thr = 2x128)
    {
        int br = tid >> 7, col = tid & 127;
        int gcol = pxh * 128 + col;
        float scA1 = __ldg(gA1) * rsqrtf(__ldg(vA1) + 1e-5f);
        float scB1 = __ldg(gB1) * rsqrtf(__ldg(vB1) + 1e-5f);
        float ghv  = axis_g(y, Hc);
        float gwv  = axis_g(gcol, Wc);
        float v = s_p[2 * br * 128 + col] + s_p[(2 * br + 1) * 128 + col];
        if (br == 0) {
            v += __ldg(aw + 64) * ghv + __ldg(aw + 65) * gwv + __ldg(abv);
            v = (v - __ldg(mA1)) * scA1 + __ldg(beA1);
        } else {
            v += __ldg(bw + 64) * ghv + __ldg(bw + 65) * gwv + __ldg(bb2);
            v = (v - __ldg(mB1)) * scB1 + __ldg(beB1);
        }
        g_att[((size_t)bb * 2 + br) * HWC + y * Wc + gcol] = v;
    }
}

// ============================================================================
// mapscale_kernel (cooperative fusion): CTA = half row (128 px x 128 ch).
//   Phase 1: 256 map values (1 per thread) -> smem.
//   Phase 2: stream, software-pipelined 2x8 load batches (MLP=8),
//            contiguous float4 stores; __launch_bounds__(256,4) caps regs.
// ============================================================================
__global__ __launch_bounds__(256, 4)
void mapscale_kernel(const float* __restrict__ wA, const float* __restrict__ wB,
                     const float* __restrict__ s1p, const float* __restrict__ s2p,
                     float* __restrict__ out, int B)
{
    __shared__ float s_m[2][128];
    int blk = blockIdx.x;
    int bb  = blk >> 9;
    int y   = (blk >> 1) & 255;
    int xh  = blk & 1;                       // which 128-px half of the row
    int tid = threadIdx.x;

    float ghmin = 0.5f / (float)(Hc / 2);
    float gwmin = 0.5f / (float)(Wc / 2);
    float ghmax = axis_g(0, Hc);
    float gwmax = axis_g(0, Wc);
    float prmin = sqrtf(ghmin * ghmin + gwmin * gwmin);
    float prmax = sqrtf(ghmax * ghmax + gwmax * gwmax);
    float kk = 2.f / (prmax - prmin);
    float cc = 1.f - prmax * kk;

    // ---- phase 1: map for this half-row, 1 (branch, px) per thread ----
    {
        int br = tid >> 7;
        int x  = xh * 128 + (tid & 127);
        const float* w  = br ? wB : wA;
        const float* ab = g_att + ((size_t)bb * 2 + br) * HWC;
        float s = 0.f;
        #pragma unroll
        for (int dy = -1; dy <= 1; dy++) {
            int yy = y + dy;
            if (yy < 0 || yy >= Hc) continue;
            float ghv = axis_g(yy, Hc);
            #pragma unroll
            for (int dxx = -1; dxx <= 1; dxx++) {
                int xn = x + dxx;
                if (xn < 0 || xn >= Wc) continue;
                float av  = ab[yy * Wc + xn];
                float gwv = axis_g(xn, Wc);
                float pr  = sqrtf(ghv * ghv + gwv * gwv);
                float prn = kk * pr + cc;
                int k = (dy + 1) * 3 + (dxx + 1);
                s += __ldg(w + k)      * av
                   + __ldg(w + 9 + k)  * ghv
                   + __ldg(w + 18 + k) * gwv
                   + __ldg(w + 27 + k) * prn;
            }
        }
        float sc = br ? __ldg(s2p) : __ldg(s1p);
        s_m[br][tid & 127] = sc / (1.f + expf(-s));
    }
    __syncthreads();

    // ---- phase 2: stream 128 ch x 128 px (4 px x 16 ch / thread) ----
    int pxg = tid & 31;                      // 4-px group (32 groups = 128 px)
    int cs  = (tid >> 5) * 16;               // channel block of 16 (8 blocks)
    int p4  = pxg * 4;
    int br  = cs >> 6;                       // 0 or 1
    float4 m = *(float4*)&s_m[br][p4];

    const __half* f0 = g_fh + (((size_t)bb * 128 + cs) * Hc + y) * Wc + xh * 128 + p4;
    float*        o0 = out  + (((size_t)bb * 128 + cs) * Hc + y) * Wc + xh * 128 + p4;

    // software pipeline: 2 batches of 8; batch k+1 loads issued before
    // processing batch k
    uint2 v0[8], v1[8];
    #pragma unroll
    for (int c = 0; c < 8; c++)
        v0[c] = __ldcs((const uint2*)(f0 + (size_t)c * HWC));
    #pragma unroll
    for (int c = 0; c < 8; c++)
        v1[c] = __ldcs((const uint2*)(f0 + (size_t)(c + 8) * HWC));
    #pragma unroll
    for (int c = 0; c < 8; c++) {
        __half2 h01 = *(__half2*)&v0[c].x;
        __half2 h23 = *(__half2*)&v0[c].y;
        float4 r;
        r.x = __low2float(h01)  * m.x;
        r.y = __high2float(h01) * m.y;
        r.z = __low2float(h23)  * m.z;
        r.w = __high2float(h23) * m.w;
        __stcs((float4*)(o0 + (size_t)c * HWC), r);
    }
    #pragma unroll
    for (int c = 0; c < 8; c++) {
        __half2 h01 = *(__half2*)&v1[c].x;
        __half2 h23 = *(__half2*)&v1[c].y;
        float4 r;
        r.x = __low2float(h01)  * m.x;
        r.y = __high2float(h01) * m.y;
        r.z = __low2float(h23)  * m.z;
        r.w = __high2float(h23) * m.w;
        __stcs((float4*)(o0 + (size_t)(c + 8) * HWC), r);
    }
}

// ============================================================================
extern "C" void kernel_launch(void* const* d_in, const int* in_sizes, int n_in,
                              void* d_out, int out_size)
{
    const float* x        = (const float*)d_in[0];
    const float* conv_a_w = (const float*)d_in[1];
    const float* conv_a_b = (const float*)d_in[2];
    const float* conv_b_w = (const float*)d_in[3];
    const float* conv_b_b = (const float*)d_in[4];
    const float* bn_a_g   = (const float*)d_in[5];
    const float* bn_a_be  = (const float*)d_in[6];
    const float* bn_a_m   = (const float*)d_in[7];
    const float* bn_a_v   = (const float*)d_in[8];
    const float* bn_b_g   = (const float*)d_in[9];
    const float* bn_b_be  = (const float*)d_in[10];
    const float* bn_b_m   = (const float*)d_in[11];
    const float* bn_b_v   = (const float*)d_in[12];
    const float* att_a_w  = (const float*)d_in[13];
    const float* att_a_b  = (const float*)d_in[14];
    const float* att_b_w  = (const float*)d_in[15];
    const float* att_b_b  = (const float*)d_in[16];
    const float* abn_a_g  = (const float*)d_in[17];
    const float* abn_a_be = (const float*)d_in[18];
    const float* abn_a_m  = (const float*)d_in[19];
    const float* abn_a_v  = (const float*)d_in[20];
    const float* abn_b_g  = (const float*)d_in[21];
    const float* abn_b_be = (const float*)d_in[22];
    const float* abn_b_m  = (const float*)d_in[23];
    const float* abn_b_v  = (const float*)d_in[24];
    const float* attn_a_w = (const float*)d_in[25];
    const float* attn_b_w = (const float*)d_in[26];
    const float* scale1   = (const float*)d_in[27];
    const float* scale2   = (const float*)d_in[28];

    int B = in_sizes[0] / (CINc * HWC);

    cudaFuncSetAttribute(conv_mma_kernel,
                         cudaFuncAttributeMaxDynamicSharedMemorySize, SMEM_TOT);

    prep_w_kernel<<<(18 * 128 * 64 + 255) / 256, 256>>>(conv_a_w, conv_b_w);
    prep_x_kernel<<<B * 1024, 256>>>(x);

    conv_mma_kernel<<<B * 512, 256, SMEM_TOT>>>(
        conv_a_b, conv_b_b,
        bn_a_g, bn_a_be, bn_a_m, bn_a_v,
        bn_b_g, bn_b_be, bn_b_m, bn_b_v,
        att_a_w, att_a_b, att_b_w, att_b_b,
        abn_a_g, abn_a_be, abn_a_m, abn_a_v,
        abn_b_g, abn_b_be, abn_b_m, abn_b_v);

    mapscale_kernel<<<B * 512, 256>>>(attn_a_w, attn_b_w, scale1, scale2,
                                      (float*)d_out, B);
}

// round 17
// speedup vs baseline: 1.0060x; 1.0060x over previous
#include <cuda_runtime.h>
#include <cuda_fp16.h>
#include <math.h>
#include <stdint.h>

#define Hc  256
#define Wc  256
#define CINc 128
#define HWC (Hc * Wc)

// ---------------- scratch (static device globals; no runtime allocation) ----
__device__ __align__(256) __half g_fh[(size_t)4 * 128 * HWC];  // post-BN features NCHW fp16
__device__ float g_att[(size_t)4 * 2 * HWC];                   // attention logits
__device__ __align__(256) __half g_xh[(size_t)4 * HWC * 128];  // x fp16, NHWC
__device__ __align__(256) __half g_wh[18 * 128 * 64];          // W fp16 [chunk][oc][k]

// ---------------- helpers ----------------------------------------------------
__device__ __forceinline__ uint32_t smem_u32(const void* p) {
    uint32_t a;
    asm("{ .reg .u64 t; cvta.to.shared.u64 t, %1; cvt.u32.u64 %0, t; }" : "=r"(a) : "l"(p));
    return a;
}
__device__ __forceinline__ void cp16(uint32_t dst, const void* src, uint32_t sz) {
    asm volatile("cp.async.cg.shared.global [%0], [%1], 16, %2;"
                 :: "r"(dst), "l"(src), "r"(sz));
}
#define CP_COMMIT() asm volatile("cp.async.commit_group;" ::: "memory")
#define CP_WAIT2()  asm volatile("cp.async.wait_group 2;" ::: "memory")

__device__ __forceinline__ void ldsm_x4(uint32_t* r, uint32_t a) {
    asm volatile("ldmatrix.sync.aligned.m8n8.x4.shared.b16 {%0,%1,%2,%3}, [%4];"
                 : "=r"(r[0]), "=r"(r[1]), "=r"(r[2]), "=r"(r[3]) : "r"(a));
}
__device__ __forceinline__ void mma16816(float* d, const uint32_t* a, const uint32_t* b) {
    asm volatile("mma.sync.aligned.m16n8k16.row.col.f32.f16.f16.f32 "
                 "{%0,%1,%2,%3},{%4,%5,%6,%7},{%8,%9},{%0,%1,%2,%3};"
                 : "+f"(d[0]), "+f"(d[1]), "+f"(d[2]), "+f"(d[3])
                 : "r"(a[0]), "r"(a[1]), "r"(a[2]), "r"(a[3]), "r"(b[0]), "r"(b[1]));
}

// position helper (matches reference)
__device__ __forceinline__ float axis_g(int i, int n) {
    float off = ((n & 1) == 0) ? 0.5f : 0.0f;
    return fabsf((float)i - (float)(n / 2) + off) / (float)(n / 2);
}

// ============================================================================
// prep_x: NCHW fp32 -> NHWC fp16 (smem transpose, coalesced both sides)
//   x read is zero-reuse -> __ldcs; loads batched for MLP
// ============================================================================
__global__ __launch_bounds__(256)
void prep_x_kernel(const float* __restrict__ x)
{
    __shared__ __half s_h[64 * 136];
    int blk = blockIdx.x;
    int bb  = blk >> 10;
    int px0 = (blk & 1023) * 64;
    int tid = threadIdx.x;
    int p = tid & 63, cq = tid >> 6;

    const float* xb = x + (size_t)bb * CINc * HWC + px0 + p;
    float v[32];
    #pragma unroll
    for (int i = 0; i < 32; i++)
        v[i] = __ldcs(xb + (size_t)(i * 4 + cq) * HWC);
    #pragma unroll
    for (int i = 0; i < 32; i++)
        s_h[p * 136 + i * 4 + cq] = __float2half(v[i]);
    __syncthreads();
    for (int i = tid; i < 64 * 16; i += 256) {
        int p2 = i >> 4, j = i & 15;
        uint4 w = *(const uint4*)&s_h[p2 * 136 + j * 8];
        size_t e = ((size_t)bb * HWC + px0 + p2) * 128 + j * 8;
        *(uint4*)(g_xh + e) = w;
    }
}

// ============================================================================
// prep_w: fp32 weights -> fp16, [chunk18][128oc][64k]
// ============================================================================
__global__ void prep_w_kernel(const float* __restrict__ wa, const float* __restrict__ wb)
{
    int idx = blockIdx.x * 256 + threadIdx.x;
    if (idx >= 18 * 128 * 64) return;
    int k  = idx & 63;
    int oc = (idx >> 6) & 127;
    int c  = idx >> 13;
    int t  = c >> 1, hf = c & 1;
    int cin = hf * 64 + k;
    float w = (oc < 64) ? wa[((size_t)oc * CINc + cin) * 9 + t]
                        : wb[((size_t)(oc - 64) * CINc + cin) * 9 + t];
    g_wh[idx] = __float2half(w);
}

// ============================================================================
// conv_mma: implicit GEMM via mma.sync fp16 (single term, fp32 accum)
//   CTA: 128 oc x 128 px; 8 warps (4 m-groups x 2 n-groups), warp tile 32x64
//   2 CTAs/SM (96 KB smem, <=128 regs)
//   K: 18 chunks of 64 (tap x cin-half); cp.async 3-stage pipeline
//   Epilogue: BN fold -> g_fh (fp16), fused 1x1 attention conv -> g_att
// ============================================================================
#define A_W  0
#define B_X  16384
#define STAGE 32768
#define SMEM_TOT (3 * STAGE)

// swizzled 16B offset inside a [row][64k] fp16 tile (row stride 128B)
__device__ __forceinline__ uint32_t swz(int row, int j16) {
    return (uint32_t)(row * 128 + ((j16 ^ (row & 7)) << 4));
}

__global__ __launch_bounds__(256, 2)
void conv_mma_kernel(const float* __restrict__ ba,  const float* __restrict__ bbv,
                     const float* __restrict__ gA,  const float* __restrict__ beA,
                     const float* __restrict__ mA,  const float* __restrict__ vA,
                     const float* __restrict__ gB,  const float* __restrict__ beB,
                     const float* __restrict__ mB,  const float* __restrict__ vB,
                     const float* __restrict__ aw,  const float* __restrict__ abv,
                     const float* __restrict__ bw,  const float* __restrict__ bb2,
                     const float* __restrict__ gA1, const float* __restrict__ beA1,
                     const float* __restrict__ mA1, const float* __restrict__ vA1,
                     const float* __restrict__ gB1, const float* __restrict__ beB1,
                     const float* __restrict__ mB1, const float* __restrict__ vB1)
{
    extern __shared__ char smem[];
    const uint32_t sb = smem_u32(smem);
    const int tid  = threadIdx.x;
    const int wid  = tid >> 5, lane = tid & 31;
    const int bb   = blockIdx.x >> 9;
    const int y    = (blockIdx.x >> 1) & 255;
    const int pxh  = blockIdx.x & 1;          // which 128-px half of the row
    const int m0   = (wid >> 1) * 32;         // warp oc base (4 m-groups)
    const int n0   = (wid & 1) * 64;          // warp px base (2 n-groups)

    float C[2][8][4];
    #pragma unroll
    for (int mt = 0; mt < 2; mt++)
        #pragma unroll
        for (int nt = 0; nt < 8; nt++)
            #pragma unroll
            for (int q = 0; q < 4; q++) C[mt][nt][q] = 0.f;

    // ---- chunk loader: cp.async into stage (c % 3), one commit ----
    auto load_chunk = [&](int c) {
        uint32_t stg = sb + (uint32_t)(c % 3) * STAGE;
        int t  = c >> 1, hf = c & 1;
        int yy = y + t / 3 - 1;
        int dx = t % 3 - 1;
        bool vy = (yy >= 0) && (yy < Hc);
        size_t arow = (size_t)c * 8192;                       // A chunk base (elems)
        size_t brow = ((size_t)(bb * Hc + yy) * Wc) * 128;    // B row base (elems)
        #pragma unroll
        for (int i = 0; i < 4; i++) {                         // A: 128 oc rows
            int idx = tid + i * 256;
            int row = idx >> 3, j = idx & 7;
            cp16(stg + A_W + swz(row, j), g_wh + arow + idx * 8, 16);
        }
        #pragma unroll
        for (int i = 0; i < 4; i++) {                         // B: 128 px rows
            int idx = tid + i * 256;
            int row = idx >> 3, j = idx & 7;
            int xx = pxh * 128 + row + dx;
            bool ok = vy && (xx >= 0) && (xx < Wc);
            size_t e = ok ? (brow + (size_t)xx * 128 + hf * 64 + j * 8) : 0;
            cp16(stg + B_X + swz(row, j), g_xh + e, ok ? 16u : 0u);
        }
        CP_COMMIT();
    };

    // prologue: prefetch chunks 0..2
    load_chunk(0);
    load_chunk(1);
    load_chunk(2);

    for (int c = 0; c < 18; c++) {
        CP_WAIT2();
        __syncthreads();
        const uint32_t stg = sb + (uint32_t)(c % 3) * STAGE;

        #pragma unroll
        for (int kg = 0; kg < 4; kg++) {
            uint32_t ah[2][4];
            #pragma unroll
            for (int mt = 0; mt < 2; mt++) {
                int row = m0 + mt * 16 + (lane & 15);
                int kc  = kg * 2 + (lane >> 4);
                ldsm_x4(ah[mt], stg + A_W + swz(row, kc));
            }
            #pragma unroll
            for (int nq = 0; nq < 4; nq++) {
                uint32_t bx[4];
                int row = n0 + nq * 16 + (lane & 7) + ((lane >> 4) << 3);
                int kc  = kg * 2 + ((lane >> 3) & 1);
                ldsm_x4(bx, stg + B_X + swz(row, kc));
                #pragma unroll
                for (int mt = 0; mt < 2; mt++)
                    #pragma unroll
                    for (int h = 0; h < 2; h++)
                        mma16816(C[mt][nq * 2 + h], ah[mt], &bx[h * 2]);
            }
        }
        __syncthreads();
        if (c + 3 < 18) load_chunk(c + 3);
        else            CP_COMMIT();
    }

    // ---- epilogue: BN fold -> g_fh (fp16), fused 1x1 att conv -> g_att ------
    float* s_p = (float*)smem;               // [4 m-groups][128 px] partials
    const int mg = wid >> 1;                 // m-group: 0,1 = branch a; 2,3 = b

    float scq4[2][2], sh4[2][2], wv4[2][2];
    __half* frow[2][2];
    #pragma unroll
    for (int mt = 0; mt < 2; mt++)
        #pragma unroll
        for (int hr = 0; hr < 2; hr++) {
            int oc = m0 + mt * 16 + (lane >> 2) + hr * 8;
            float sc, sh;
            if (oc < 64) {
                sc = gA[oc] * rsqrtf(vA[oc] + 1e-3f);
                sh = beA[oc] - mA[oc] * sc + ba[oc] * sc;
                wv4[mt][hr] = __ldg(aw + oc);
            } else {
                int o = oc - 64;
                sc = gB[o] * rsqrtf(vB[o] + 1e-3f);
                sh = beB[o] - mB[o] * sc + bbv[o] * sc;
                wv4[mt][hr] = __ldg(bw + o);
            }
            scq4[mt][hr] = sc;
            sh4[mt][hr]  = sh;
            frow[mt][hr] = g_fh + (((size_t)bb * 128 + oc) * Hc + y) * Wc + pxh * 128;
        }

    #pragma unroll
    for (int nt = 0; nt < 8; nt++) {
        int col = n0 + nt * 8 + 2 * (lane & 3);
        float v0 = 0.f, v1 = 0.f;
        #pragma unroll
        for (int mt = 0; mt < 2; mt++)
            #pragma unroll
            for (int hr = 0; hr < 2; hr++) {
                float f0 = C[mt][nt][hr * 2 + 0] * scq4[mt][hr] + sh4[mt][hr];
                float f1 = C[mt][nt][hr * 2 + 1] * scq4[mt][hr] + sh4[mt][hr];
                *(__half2*)(frow[mt][hr] + col) = __floats2half2_rn(f0, f1);
                v0 += wv4[mt][hr] * f0;
                v1 += wv4[mt][hr] * f1;
            }
        // reduce across the 8 row-lanes (same lane&3)
        #pragma unroll
        for (int d = 16; d >= 4; d >>= 1) {
            v0 += __shfl_down_sync(0xffffffffu, v0, d);
            v1 += __shfl_down_sync(0xffffffffu, v1, d);
        }
        if ((lane >> 2) == 0) {
            s_p[mg * 128 + col]     = v0;
            s_p[mg * 128 + col + 1] = v1;
        }
    }
    __syncthreads();

    // finalize attention logits: +gh/gw terms +bias, BN, store (256 thr = 2x128)
    {
        int br = tid >> 7, col = tid & 127;
        int gcol = pxh * 128 + col;
        float scA1 = __ldg(gA1) * rsqrtf(__ldg(vA1) + 1e-5f);
        float scB1 = __ldg(gB1) * rsqrtf(__ldg(vB1) + 1e-5f);
        float ghv  = axis_g(y, Hc);
        float gwv  = axis_g(gcol, Wc);
        float v = s_p[2 * br * 128 + col] + s_p[(2 * br + 1) * 128 + col];
        if (br == 0) {
            v += __ldg(aw + 64) * ghv + __ldg(aw + 65) * gwv + __ldg(abv);
            v = (v - __ldg(mA1)) * scA1 + __ldg(beA1);
        } else {
            v += __ldg(bw + 64) * ghv + __ldg(bw + 65) * gwv + __ldg(bb2);
            v = (v - __ldg(mB1)) * scB1 + __ldg(beB1);
        }
        g_att[((size_t)bb * 2 + br) * HWC + y * Wc + gcol] = v;
    }
}

// ============================================================================
// mapscale_kernel (cooperative fusion): CTA = half row (128 px x 128 ch).
//   Phase 1: 256 map values (1 per thread) -> smem.
//   Phase 2: stream, 2 independent bursts of 8 loads (MLP=8, ~44 regs live),
//            contiguous float4 stores.
// ============================================================================
__global__ __launch_bounds__(256)
void mapscale_kernel(const float* __restrict__ wA, const float* __restrict__ wB,
                     const float* __restrict__ s1p, const float* __restrict__ s2p,
                     float* __restrict__ out, int B)
{
    __shared__ float s_m[2][128];
    int blk = blockIdx.x;
    int bb  = blk >> 9;
    int y   = (blk >> 1) & 255;
    int xh  = blk & 1;                       // which 128-px half of the row
    int tid = threadIdx.x;

    float ghmin = 0.5f / (float)(Hc / 2);
    float gwmin = 0.5f / (float)(Wc / 2);
    float ghmax = axis_g(0, Hc);
    float gwmax = axis_g(0, Wc);
    float prmin = sqrtf(ghmin * ghmin + gwmin * gwmin);
    float prmax = sqrtf(ghmax * ghmax + gwmax * gwmax);
    float kk = 2.f / (prmax - prmin);
    float cc = 1.f - prmax * kk;

    // ---- phase 1: map for this half-row, 1 (branch, px) per thread ----
    {
        int br = tid >> 7;
        int x  = xh * 128 + (tid & 127);
        const float* w  = br ? wB : wA;
        const float* ab = g_att + ((size_t)bb * 2 + br) * HWC;
        float s = 0.f;
        #pragma unroll
        for (int dy = -1; dy <= 1; dy++) {
            int yy = y + dy;
            if (yy < 0 || yy >= Hc) continue;
            float ghv = axis_g(yy, Hc);
            #pragma unroll
            for (int dxx = -1; dxx <= 1; dxx++) {
                int xn = x + dxx;
                if (xn < 0 || xn >= Wc) continue;
                float av  = ab[yy * Wc + xn];
                float gwv = axis_g(xn, Wc);
                float pr  = sqrtf(ghv * ghv + gwv * gwv);
                float prn = kk * pr + cc;
                int k = (dy + 1) * 3 + (dxx + 1);
                s += __ldg(w + k)      * av
                   + __ldg(w + 9 + k)  * ghv
                   + __ldg(w + 18 + k) * gwv
                   + __ldg(w + 27 + k) * prn;
            }
        }
        float sc = br ? __ldg(s2p) : __ldg(s1p);
        s_m[br][tid & 127] = sc / (1.f + expf(-s));
    }
    __syncthreads();

    // ---- phase 2: stream 128 ch x 128 px (4 px x 16 ch / thread) ----
    int pxg = tid & 31;                      // 4-px group (32 groups = 128 px)
    int cs  = (tid >> 5) * 16;               // channel block of 16 (8 blocks)
    int p4  = pxg * 4;
    int br  = cs >> 6;                       // 0 or 1
    float4 m = *(float4*)&s_m[br][p4];

    const __half* f0 = g_fh + (((size_t)bb * 128 + cs) * Hc + y) * Wc + xh * 128 + p4;
    float*        o0 = out  + (((size_t)bb * 128 + cs) * Hc + y) * Wc + xh * 128 + p4;

    // two independent 8-load bursts (keeps live state at 8 uint2)
    #pragma unroll
    for (int half = 0; half < 2; half++) {
        uint2 v[8];
        #pragma unroll
        for (int c = 0; c < 8; c++)
            v[c] = __ldcs((const uint2*)(f0 + (size_t)(half * 8 + c) * HWC));
        #pragma unroll
        for (int c = 0; c < 8; c++) {
            __half2 h01 = *(__half2*)&v[c].x;
            __half2 h23 = *(__half2*)&v[c].y;
            float4 r;
            r.x = __low2float(h01)  * m.x;
            r.y = __high2float(h01) * m.y;
            r.z = __low2float(h23)  * m.z;
            r.w = __high2float(h23) * m.w;
            __stcs((float4*)(o0 + (size_t)(half * 8 + c) * HWC), r);
        }
    }
}

// ============================================================================
extern "C" void kernel_launch(void* const* d_in, const int* in_sizes, int n_in,
                              void* d_out, int out_size)
{
    const float* x        = (const float*)d_in[0];
    const float* conv_a_w = (const float*)d_in[1];
    const float* conv_a_b = (const float*)d_in[2];
    const float* conv_b_w = (const float*)d_in[3];
    const float* conv_b_b = (const float*)d_in[4];
    const float* bn_a_g   = (const float*)d_in[5];
    const float* bn_a_be  = (const float*)d_in[6];
    const float* bn_a_m   = (const float*)d_in[7];
    const float* bn_a_v   = (const float*)d_in[8];
    const float* bn_b_g   = (const float*)d_in[9];
    const float* bn_b_be  = (const float*)d_in[10];
    const float* bn_b_m   = (const float*)d_in[11];
    const float* bn_b_v   = (const float*)d_in[12];
    const float* att_a_w  = (const float*)d_in[13];
    const float* att_a_b  = (const float*)d_in[14];
    const float* att_b_w  = (const float*)d_in[15];
    const float* att_b_b  = (const float*)d_in[16];
    const float* abn_a_g  = (const float*)d_in[17];
    const float* abn_a_be = (const float*)d_in[18];
    const float* abn_a_m  = (const float*)d_in[19];
    const float* abn_a_v  = (const float*)d_in[20];
    const float* abn_b_g  = (const float*)d_in[21];
    const float* abn_b_be = (const float*)d_in[22];
    const float* abn_b_m  = (const float*)d_in[23];
    const float* abn_b_v  = (const float*)d_in[24];
    const float* attn_a_w = (const float*)d_in[25];
    const float* attn_b_w = (const float*)d_in[26];
    const float* scale1   = (const float*)d_in[27];
    const float* scale2   = (const float*)d_in[28];

    int B = in_sizes[0] / (CINc * HWC);

    cudaFuncSetAttribute(conv_mma_kernel,
                         cudaFuncAttributeMaxDynamicSharedMemorySize, SMEM_TOT);

    prep_w_kernel<<<(18 * 128 * 64 + 255) / 256, 256>>>(conv_a_w, conv_b_w);
    prep_x_kernel<<<B * 1024, 256>>>(x);

    conv_mma_kernel<<<B * 512, 256, SMEM_TOT>>>(
        conv_a_b, conv_b_b,
        bn_a_g, bn_a_be, bn_a_m, bn_a_v,
        bn_b_g, bn_b_be, bn_b_m, bn_b_v,
        att_a_w, att_a_b, att_b_w, att_b_b,
        abn_a_g, abn_a_be, abn_a_m, abn_a_v,
        abn_b_g, abn_b_be, abn_b_m, abn_b_v);

    mapscale_kernel<<<B * 512, 256>>>(attn_a_w, attn_b_w, scale1, scale2,
                                      (float*)d_out, B);
}